// round 1
// baseline (speedup 1.0000x reference)
#include <cuda_runtime.h>

// Problem constants (from reference: B=16, C=1, H=W=1024, PATCH=5)
#define HD   1024
#define WD   1024
#define OD   1016          // H - 8
#define TILE 32            // final outputs per block side
#define RAW  40            // TILE + 8  (raw input halo tile)
#define MID  36            // TILE + 4  (xc / p intermediate tile)

__global__ __launch_bounds__(256)
void cov_fused_kernel(const float* __restrict__ x,
                      const float* __restrict__ y,
                      float* __restrict__ out)
{
    __shared__ __align__(16) float sA[RAW * RAW];   // raw x tile, then raw y tile (1600 f)
    __shared__ float sH[RAW * MID];                 // horizontal 5-sums of raw   (1440 f)
    __shared__ float sXC[MID * MID];                // xc, then p = xc*yc         (1296 f)
    __shared__ float sPH[MID * TILE];               // horizontal 5-sums of p     (1152 f)

    const int tid  = threadIdx.x;
    const int ox0  = blockIdx.x * TILE;
    const int oy0  = blockIdx.y * TILE;
    const long img = (long)blockIdx.z * (long)(HD * WD);
    const float inv25 = 1.0f / 25.0f;

    const bool interior = (ox0 + RAW <= WD) && (oy0 + RAW <= HD);

    // ---- tile loader: 40x40 halo tile into sA ----
    auto load_tile = [&](const float* __restrict__ g) {
        if (interior) {
            // vectorized: 40 rows x 10 float4 = 400 float4 loads
            for (int i = tid; i < RAW * (RAW / 4); i += 256) {
                int r = i / (RAW / 4), c4 = i % (RAW / 4);
                const float4 v = *reinterpret_cast<const float4*>(
                    g + (long)(oy0 + r) * WD + ox0 + c4 * 4);
                *reinterpret_cast<float4*>(&sA[r * RAW + c4 * 4]) = v;
            }
        } else {
            for (int i = tid; i < RAW * RAW; i += 256) {
                int r = i / RAW, c = i % RAW;
                int gy = min(oy0 + r, HD - 1);
                int gx = min(ox0 + c, WD - 1);
                sA[i] = g[(long)gy * WD + gx];
            }
        }
    };

    // ---- horizontal 5-sum of sA -> sH  (40 rows x 36 cols; runs of 6) ----
    auto hsum_raw = [&]() {
        if (tid < 240) {
            int r  = tid / 6;
            int c0 = (tid % 6) * 6;
            const float* row = sA + r * RAW + c0;
            float s = row[0] + row[1] + row[2] + row[3] + row[4];
            float* hrow = sH + r * MID + c0;
            hrow[0] = s;
            #pragma unroll
            for (int k = 1; k < 6; k++) { s += row[k + 4] - row[k - 1]; hrow[k] = s; }
        }
    };

    // ---- vertical 5-sum of sH, subtract from center of sA ->
    //      mode 0: sXC = center - mean ;  mode 1: sXC *= (center - mean)
    auto vsum_center = [&](bool mul) {
        if (tid < 216) {
            int c  = tid % MID;
            int r0 = (tid / MID) * 6;
            float s = sH[r0 * MID + c] + sH[(r0 + 1) * MID + c] + sH[(r0 + 2) * MID + c]
                    + sH[(r0 + 3) * MID + c] + sH[(r0 + 4) * MID + c];
            #pragma unroll
            for (int k = 0; k < 6; k++) {
                if (k) s += sH[(r0 + k + 4) * MID + c] - sH[(r0 + k - 1) * MID + c];
                float v = sA[(r0 + k + 2) * RAW + (c + 2)] - s * inv25;
                int idx = (r0 + k) * MID + c;
                sXC[idx] = mul ? sXC[idx] * v : v;
            }
        }
    };

    // ===== pipeline =====
    load_tile(x + img);            __syncthreads();
    hsum_raw();                    __syncthreads();
    vsum_center(false);            __syncthreads();   // sXC = xc

    load_tile(y + img);            __syncthreads();
    hsum_raw();                    __syncthreads();
    vsum_center(true);             __syncthreads();   // sXC = xc * yc = p

    // ---- horizontal 5-sum of p -> sPH  (36 rows x 32 cols; runs of 8) ----
    if (tid < 144) {
        int r  = tid / 4;
        int c0 = (tid % 4) * 8;
        const float* row = sXC + r * MID + c0;
        float s = row[0] + row[1] + row[2] + row[3] + row[4];
        float* ph = sPH + r * TILE + c0;
        ph[0] = s;
        #pragma unroll
        for (int k = 1; k < 8; k++) { s += row[k + 4] - row[k - 1]; ph[k] = s; }
    }
    __syncthreads();

    // ---- vertical 5-sum of sPH -> global out  (32 cols; runs of 8 rows) ----
    if (tid < 128) {
        int c  = tid % TILE;
        int r0 = (tid / TILE) * 8;
        float s = sPH[r0 * TILE + c] + sPH[(r0 + 1) * TILE + c] + sPH[(r0 + 2) * TILE + c]
                + sPH[(r0 + 3) * TILE + c] + sPH[(r0 + 4) * TILE + c];
        float* o = out + (long)blockIdx.z * (long)(OD * OD);
        #pragma unroll
        for (int k = 0; k < 8; k++) {
            if (k) s += sPH[(r0 + k + 4) * TILE + c] - sPH[(r0 + k - 1) * TILE + c];
            int oy = oy0 + r0 + k;
            int ox = ox0 + c;
            if (oy < OD && ox < OD) o[(long)oy * OD + ox] = s * inv25;
        }
    }
}

extern "C" void kernel_launch(void* const* d_in, const int* in_sizes, int n_in,
                              void* d_out, int out_size)
{
    const float* x = (const float*)d_in[0];
    const float* y = (const float*)d_in[1];
    float* out = (float*)d_out;

    const int B = in_sizes[0] / (HD * WD);          // 16
    dim3 grid((OD + TILE - 1) / TILE, (OD + TILE - 1) / TILE, B);
    cov_fused_kernel<<<grid, 256>>>(x, y, out);
}

// round 4
// speedup vs baseline: 1.5183x; 1.5183x over previous
#include <cuda_runtime.h>

#define HD 1024
#define WD 1024
#define OD 1016
#define SEG_OUT 62                 // output rows per warp-segment
#define SEG_IN  70                 // SEG_OUT + 8, divisible by 5
#define NSEG    17                 // ceil(1016/62)
#define NSTRIP  9                  // 120 output cols per warp strip (lanes 1..30)
#define WPB     8                  // warps per block

static __device__ __forceinline__ float4 f4add(float4 a, float4 b) {
    return make_float4(a.x + b.x, a.y + b.y, a.z + b.z, a.w + b.w);
}
static __device__ __forceinline__ float4 f4sub(float4 a, float4 b) {
    return make_float4(a.x - b.x, a.y - b.y, a.z - b.z, a.w - b.w);
}

// Horizontal 5-sum centered at each of this thread's 4 columns.
// Thread lane l owns input cols 4l..4l+3 of a 128-col warp strip.
static __device__ __forceinline__ float4 hsum5(const float4 v) {
    const unsigned FULL = 0xffffffffu;
    float lm2 = __shfl_up_sync(FULL, v.z, 1);   // col 4l-2
    float lm1 = __shfl_up_sync(FULL, v.w, 1);   // col 4l-1
    float rp1 = __shfl_down_sync(FULL, v.x, 1); // col 4l+4
    float rp2 = __shfl_down_sync(FULL, v.y, 1); // col 4l+5
    float s012 = v.x + v.y + v.z;
    float4 h;
    h.x = lm2 + lm1 + s012;
    h.y = lm1 + s012 + v.w;
    h.z = s012 + v.w + rp1;
    h.w = (v.y + v.z) + (v.w + rp1) + rp2;
    return h;
}

__global__ void __launch_bounds__(256, 2)
cov_sliding(const float* __restrict__ xg, const float* __restrict__ yg,
            float* __restrict__ outg, int nbatch)
{
    const int warp = threadIdx.x >> 5;
    const int lane = threadIdx.x & 31;
    const int task = blockIdx.x * WPB + warp;
    const int total = nbatch * NSTRIP * NSEG;
    if (task >= total) return;

    const int seg   = task % NSEG;
    const int strip = (task / NSEG) % NSTRIP;
    const int b     = task / (NSEG * NSTRIP);

    const int gcol = strip * 120 + lane * 4;            // first input col this thread owns
    const int lcol = gcol > (WD - 4) ? (WD - 4) : gcol; // clamped load col (strip 8 edge)
    const int s0   = seg * SEG_OUT;                     // first input row of segment

    const float* xb = xg + (size_t)b * HD * WD + lcol;
    const float* yb = yg + (size_t)b * HD * WD + lcol;
    float*       ob = outg + (size_t)b * OD * OD;

    const int  ocol = gcol - 4;                         // output col for this thread
    // lanes 1..30 emit -> exactly 120 non-overlapping cols per strip; lane 31's
    // p.z/p.w are invalid (no lane-32 halo) so it must never write.
    const bool emit_lane = (lane >= 1) && (lane <= 30) && (ocol + 4 <= OD);

    const float4 z4 = make_float4(0.f, 0.f, 0.f, 0.f);
    float4 hxr[5], hyr[5], hpr[5];                      // depth-5 register rings
    float4 vsx = z4, vsy = z4, vsp = z4;                // running vertical 5-sums
#pragma unroll
    for (int i = 0; i < 5; ++i) { hxr[i] = z4; hyr[i] = z4; hpr[i] = z4; }

    const float inv25 = 1.0f / 25.0f;

    for (int g = 0; g < SEG_IN / 5; ++g) {
        if (s0 + g * 5 - 8 >= OD) break;                // last segment: stop early
#pragma unroll
        for (int ph = 0; ph < 5; ++ph) {
            const int t = g * 5 + ph;                   // local row iteration
            int r  = s0 + t;       r  = r  > HD - 1 ? HD - 1 : r;
            int r2 = s0 + t - 2;   r2 = r2 < 0 ? 0 : (r2 > HD - 1 ? HD - 1 : r2);

            // current row (DRAM/L2) + center row re-load (guaranteed L1 hit)
            const float4 xv = *reinterpret_cast<const float4*>(xb + (size_t)r  * WD);
            const float4 yv = *reinterpret_cast<const float4*>(yb + (size_t)r  * WD);
            const float4 xo = *reinterpret_cast<const float4*>(xb + (size_t)r2 * WD);
            const float4 yo = *reinterpret_cast<const float4*>(yb + (size_t)r2 * WD);

            // horizontal 5-sums of raw rows
            const float4 hx = hsum5(xv);
            const float4 hy = hsum5(yv);

            // vertical sliding window (rows t-4..t after update)
            vsx = f4add(vsx, f4sub(hx, hxr[ph]));  hxr[ph] = hx;
            vsy = f4add(vsy, f4sub(hy, hyr[ph]));  hyr[ph] = hy;

            // centered deviations at row t-2, product p = xc*yc
            float4 p;
            p.x = (xo.x - vsx.x * inv25) * (yo.x - vsy.x * inv25);
            p.y = (xo.y - vsx.y * inv25) * (yo.y - vsy.y * inv25);
            p.z = (xo.z - vsx.z * inv25) * (yo.z - vsy.z * inv25);
            p.w = (xo.w - vsx.w * inv25) * (yo.w - vsy.w * inv25);
            if (t < 4) p = z4;                          // priming rows: keep vsp exact

            const float4 hp = hsum5(p);
            vsp = f4add(vsp, f4sub(hp, hpr[ph]));  hpr[ph] = hp;

            // output row s0 + t - 8 (second box-mean centered at row t-4)
            const int orow = s0 + t - 8;
            if (t >= 8 && orow < OD && emit_lane) {
                float4 o = make_float4(vsp.x * inv25, vsp.y * inv25,
                                       vsp.z * inv25, vsp.w * inv25);
                *reinterpret_cast<float4*>(ob + (size_t)orow * OD + ocol) = o;
            }
        }
    }
}

extern "C" void kernel_launch(void* const* d_in, const int* in_sizes, int n_in,
                              void* d_out, int out_size)
{
    const float* x = (const float*)d_in[0];
    const float* y = (const float*)d_in[1];
    float* out = (float*)d_out;

    const int nbatch = in_sizes[0] / (HD * WD);         // 16
    const int total  = nbatch * NSTRIP * NSEG;          // 2448 warp-tasks
    const int blocks = (total + WPB - 1) / WPB;         // 306
    cov_sliding<<<blocks, WPB * 32>>>(x, y, out, nbatch);
}

// round 5
// speedup vs baseline: 1.8436x; 1.2143x over previous
#include <cuda_runtime.h>

#define HD 1024
#define WD 1024
#define OD 1016
#define SEG_OUT 64                 // output rows per warp-segment
#define SEG_IN  72                 // SEG_OUT + 8
#define NSEG    16                 // 16*64 = 1024 >= 1016
#define NSTRIP  9                  // 120 output cols per warp strip (lanes 1..30)
#define WPB     8                  // warps per block
// tasks = 16 batches * 9 strips * 16 segs = 2304 warps = 288 blocks
// capacity = 148 SMs * 2 blocks/SM = 296 -> exactly one wave (no tail)

static __device__ __forceinline__ float4 f4add(float4 a, float4 b) {
    return make_float4(a.x + b.x, a.y + b.y, a.z + b.z, a.w + b.w);
}
static __device__ __forceinline__ float4 f4sub(float4 a, float4 b) {
    return make_float4(a.x - b.x, a.y - b.y, a.z - b.z, a.w - b.w);
}

// Horizontal 5-sum centered at each of this thread's 4 columns.
// Thread lane l owns input cols 4l..4l+3 of a 128-col warp strip.
static __device__ __forceinline__ float4 hsum5(const float4 v) {
    const unsigned FULL = 0xffffffffu;
    float lm2 = __shfl_up_sync(FULL, v.z, 1);   // col 4l-2
    float lm1 = __shfl_up_sync(FULL, v.w, 1);   // col 4l-1
    float rp1 = __shfl_down_sync(FULL, v.x, 1); // col 4l+4
    float rp2 = __shfl_down_sync(FULL, v.y, 1); // col 4l+5
    float s012 = v.x + v.y + v.z;
    float4 h;
    h.x = lm2 + lm1 + s012;
    h.y = lm1 + s012 + v.w;
    h.z = s012 + v.w + rp1;
    h.w = (v.y + v.z) + (v.w + rp1) + rp2;
    return h;
}

__global__ void __launch_bounds__(256, 2)
cov_sliding(const float* __restrict__ xg, const float* __restrict__ yg,
            float* __restrict__ outg, int nbatch)
{
    const int warp = threadIdx.x >> 5;
    const int lane = threadIdx.x & 31;
    const int task = blockIdx.x * WPB + warp;
    const int total = nbatch * NSTRIP * NSEG;
    if (task >= total) return;

    const int seg   = task % NSEG;
    const int strip = (task / NSEG) % NSTRIP;
    const int b     = task / (NSEG * NSTRIP);

    const int gcol = strip * 120 + lane * 4;            // first input col this thread owns
    const int lcol = gcol > (WD - 4) ? (WD - 4) : gcol; // clamped load col (strip 8 edge)
    const int s0   = seg * SEG_OUT;                     // first input row of segment

    const float* xb = xg + (size_t)b * HD * WD + lcol;
    const float* yb = yg + (size_t)b * HD * WD + lcol;
    float*       ob = outg + (size_t)b * OD * OD;

    const int  ocol = gcol - 4;                         // output col for this thread
    // lanes 1..30 emit -> exactly 120 non-overlapping cols per strip; lane 31's
    // p.z/p.w are invalid (no lane-32 halo) so it must never write.
    const bool emit_lane = (lane >= 1) && (lane <= 30) && (ocol + 4 <= OD);
    const int  orow_end  = (s0 + SEG_OUT < OD) ? (s0 + SEG_OUT) : OD; // segment-exclusive rows

    const float4 z4 = make_float4(0.f, 0.f, 0.f, 0.f);
    float4 hxr[5], hyr[5], hpr[5];                      // depth-5 register rings
    float4 vsx = z4, vsy = z4, vsp = z4;                // running vertical 5-sums
#pragma unroll
    for (int i = 0; i < 5; ++i) { hxr[i] = z4; hyr[i] = z4; hpr[i] = z4; }

    const float inv25 = 1.0f / 25.0f;

    // 15 groups of 5 rows covers t = 0..74 (need t up to SEG_OUT+7 = 71)
    for (int g = 0; g < (SEG_IN + 4) / 5; ++g) {
        if (s0 + g * 5 - 8 >= OD) break;                // last segment: stop early
#pragma unroll
        for (int ph = 0; ph < 5; ++ph) {
            const int t = g * 5 + ph;                   // local row iteration
            int r  = s0 + t;       r  = r  > HD - 1 ? HD - 1 : r;
            int r2 = s0 + t - 2;   r2 = r2 < 0 ? 0 : (r2 > HD - 1 ? HD - 1 : r2);

            // current row (DRAM/L2) + center row re-load (guaranteed L1 hit)
            const float4 xv = *reinterpret_cast<const float4*>(xb + (size_t)r  * WD);
            const float4 yv = *reinterpret_cast<const float4*>(yb + (size_t)r  * WD);
            const float4 xo = *reinterpret_cast<const float4*>(xb + (size_t)r2 * WD);
            const float4 yo = *reinterpret_cast<const float4*>(yb + (size_t)r2 * WD);

            // horizontal 5-sums of raw rows
            const float4 hx = hsum5(xv);
            const float4 hy = hsum5(yv);

            // vertical sliding window (rows t-4..t after update)
            vsx = f4add(vsx, f4sub(hx, hxr[ph]));  hxr[ph] = hx;
            vsy = f4add(vsy, f4sub(hy, hyr[ph]));  hyr[ph] = hy;

            // centered deviations at row t-2, product p = xc*yc
            float4 p;
            p.x = (xo.x - vsx.x * inv25) * (yo.x - vsy.x * inv25);
            p.y = (xo.y - vsx.y * inv25) * (yo.y - vsy.y * inv25);
            p.z = (xo.z - vsx.z * inv25) * (yo.z - vsy.z * inv25);
            p.w = (xo.w - vsx.w * inv25) * (yo.w - vsy.w * inv25);
            if (t < 4) p = z4;                          // priming rows: keep vsp exact

            const float4 hp = hsum5(p);
            vsp = f4add(vsp, f4sub(hp, hpr[ph]));  hpr[ph] = hp;

            // output row s0 + t - 8 (second box-mean centered at row t-4)
            const int orow = s0 + t - 8;
            if (t >= 8 && orow < orow_end && emit_lane) {
                float4 o = make_float4(vsp.x * inv25, vsp.y * inv25,
                                       vsp.z * inv25, vsp.w * inv25);
                *reinterpret_cast<float4*>(ob + (size_t)orow * OD + ocol) = o;
            }
        }
    }
}

extern "C" void kernel_launch(void* const* d_in, const int* in_sizes, int n_in,
                              void* d_out, int out_size)
{
    const float* x = (const float*)d_in[0];
    const float* y = (const float*)d_in[1];
    float* out = (float*)d_out;

    const int nbatch = in_sizes[0] / (HD * WD);         // 16
    const int total  = nbatch * NSTRIP * NSEG;          // 2304 warp-tasks
    const int blocks = (total + WPB - 1) / WPB;         // 288
    cov_sliding<<<blocks, WPB * 32>>>(x, y, out, nbatch);
}

// round 6
// speedup vs baseline: 2.0524x; 1.1133x over previous
#include <cuda_runtime.h>

#define HD 1024
#define WD 1024
#define OD 1016
#define SEG_OUT 43                 // output rows per warp-segment
#define NSEG    24                 // 24*43 = 1032 >= 1016
#define NSTRIP  9                  // 120 output cols per warp strip (lanes 1..30)
#define WPB     8                  // warps per block
// tasks = 16 batches * 9 strips * 24 segs = 3456 warps = 432 blocks
// capacity at 3 blocks/SM = 148*3 = 444 -> single wave

static __device__ __forceinline__ float4 f4add(float4 a, float4 b) {
    return make_float4(a.x + b.x, a.y + b.y, a.z + b.z, a.w + b.w);
}
static __device__ __forceinline__ float4 f4sub(float4 a, float4 b) {
    return make_float4(a.x - b.x, a.y - b.y, a.z - b.z, a.w - b.w);
}

// Horizontal 5-sum centered at each of this thread's 4 columns.
static __device__ __forceinline__ float4 hsum5(const float4 v) {
    const unsigned FULL = 0xffffffffu;
    float lm2 = __shfl_up_sync(FULL, v.z, 1);   // col 4l-2
    float lm1 = __shfl_up_sync(FULL, v.w, 1);   // col 4l-1
    float rp1 = __shfl_down_sync(FULL, v.x, 1); // col 4l+4
    float rp2 = __shfl_down_sync(FULL, v.y, 1); // col 4l+5
    float s012 = v.x + v.y + v.z;
    float4 h;
    h.x = lm2 + lm1 + s012;
    h.y = lm1 + s012 + v.w;
    h.z = s012 + v.w + rp1;
    h.w = (v.y + v.z) + (v.w + rp1) + rp2;
    return h;
}

__global__ void __launch_bounds__(256, 3)
cov_sliding(const float* __restrict__ xg, const float* __restrict__ yg,
            float* __restrict__ outg, int nbatch)
{
    const int warp = threadIdx.x >> 5;
    const int lane = threadIdx.x & 31;
    const int task = blockIdx.x * WPB + warp;
    const int total = nbatch * NSTRIP * NSEG;
    if (task >= total) return;

    const int seg   = task % NSEG;
    const int strip = (task / NSEG) % NSTRIP;
    const int b     = task / (NSEG * NSTRIP);

    const int gcol = strip * 120 + lane * 4;            // first input col this thread owns
    const int lcol = gcol > (WD - 4) ? (WD - 4) : gcol; // clamped load col (strip 8 edge)
    const int s0   = seg * SEG_OUT;                     // first input row of segment

    const float* xb = xg + (size_t)b * HD * WD + lcol;
    const float* yb = yg + (size_t)b * HD * WD + lcol;
    float*       ob = outg + (size_t)b * OD * OD;

    const int  ocol = gcol - 4;
    const bool emit_lane = (lane >= 1) && (lane <= 30) && (ocol + 4 <= OD);
    const int  orow_end  = (s0 + SEG_OUT < OD) ? (s0 + SEG_OUT) : OD;

    const float4 z4 = make_float4(0.f, 0.f, 0.f, 0.f);
    float4 vcx = z4, vcy = z4;         // vertical 5-row column sums of raw x / y
    float4 vsp = z4;                   // vertical 5-row sum of hp
    float4 hpr[5];                     // depth-5 ring of hp only
#pragma unroll
    for (int i = 0; i < 5; ++i) hpr[i] = z4;

    const float inv25 = 1.0f / 25.0f;

    // ---- prologue: t = 0..4 (prime vcx/vcy; first p at t=4) ----
#pragma unroll
    for (int t = 0; t < 4; ++t) {
        const int r = s0 + t;          // s0 <= 989, no clamp needed here
        vcx = f4add(vcx, *reinterpret_cast<const float4*>(xb + (size_t)r * WD));
        vcy = f4add(vcy, *reinterpret_cast<const float4*>(yb + (size_t)r * WD));
    }
    {
        const int r  = s0 + 4;
        const int r2 = s0 + 2;
        const float4 xv = *reinterpret_cast<const float4*>(xb + (size_t)r  * WD);
        const float4 yv = *reinterpret_cast<const float4*>(yb + (size_t)r  * WD);
        const float4 xo = *reinterpret_cast<const float4*>(xb + (size_t)r2 * WD);
        const float4 yo = *reinterpret_cast<const float4*>(yb + (size_t)r2 * WD);
        vcx = f4add(vcx, xv);
        vcy = f4add(vcy, yv);
        const float4 mx = hsum5(vcx);
        const float4 my = hsum5(vcy);
        float4 p;
        p.x = (xo.x - mx.x * inv25) * (yo.x - my.x * inv25);
        p.y = (xo.y - mx.y * inv25) * (yo.y - my.y * inv25);
        p.z = (xo.z - mx.z * inv25) * (yo.z - my.z * inv25);
        p.w = (xo.w - mx.w * inv25) * (yo.w - my.w * inv25);
        const float4 hp = hsum5(p);
        vsp = f4add(vsp, hp);
        hpr[4] = hp;
    }

    // ---- main loop: t = 5 .. SEG_OUT+7, groups of 5 ----
    for (int t5 = 5; t5 < SEG_OUT + 8; t5 += 5) {
        if (s0 + t5 - 8 >= orow_end) break;   // no outputs remain
#pragma unroll
        for (int ph = 0; ph < 5; ++ph) {
            const int t = t5 + ph;
            int r  = s0 + t;      r  = r  > HD - 1 ? HD - 1 : r;
            int r5 = s0 + t - 5;  r5 = r5 > HD - 1 ? HD - 1 : r5;   // same clamp law as r
            int r2 = s0 + t - 2;  r2 = r2 > HD - 1 ? HD - 1 : r2;

            const float4 xv  = *reinterpret_cast<const float4*>(xb + (size_t)r  * WD);
            const float4 yv  = *reinterpret_cast<const float4*>(yb + (size_t)r  * WD);
            const float4 xv5 = *reinterpret_cast<const float4*>(xb + (size_t)r5 * WD); // L1 hit
            const float4 yv5 = *reinterpret_cast<const float4*>(yb + (size_t)r5 * WD); // L1 hit
            const float4 xo  = *reinterpret_cast<const float4*>(xb + (size_t)r2 * WD); // L1 hit
            const float4 yo  = *reinterpret_cast<const float4*>(yb + (size_t)r2 * WD); // L1 hit

            vcx = f4add(vcx, f4sub(xv, xv5));   // rows t-4..t
            vcy = f4add(vcy, f4sub(yv, yv5));

            const float4 mx = hsum5(vcx);
            const float4 my = hsum5(vcy);

            float4 p;
            p.x = (xo.x - mx.x * inv25) * (yo.x - my.x * inv25);
            p.y = (xo.y - mx.y * inv25) * (yo.y - my.y * inv25);
            p.z = (xo.z - mx.z * inv25) * (yo.z - my.z * inv25);
            p.w = (xo.w - mx.w * inv25) * (yo.w - my.w * inv25);

            const float4 hp = hsum5(p);
            vsp = f4add(vsp, f4sub(hp, hpr[ph]));
            hpr[ph] = hp;

            const int orow = s0 + t - 8;
            if (orow >= 0 && orow < orow_end && emit_lane) {
                float4 o = make_float4(vsp.x * inv25, vsp.y * inv25,
                                       vsp.z * inv25, vsp.w * inv25);
                *reinterpret_cast<float4*>(ob + (size_t)orow * OD + ocol) = o;
            }
        }
    }
}

extern "C" void kernel_launch(void* const* d_in, const int* in_sizes, int n_in,
                              void* d_out, int out_size)
{
    const float* x = (const float*)d_in[0];
    const float* y = (const float*)d_in[1];
    float* out = (float*)d_out;

    const int nbatch = in_sizes[0] / (HD * WD);         // 16
    const int total  = nbatch * NSTRIP * NSEG;          // 3456 warp-tasks
    const int blocks = (total + WPB - 1) / WPB;         // 432
    cov_sliding<<<blocks, WPB * 32>>>(x, y, out, nbatch);
}